// round 16
// baseline (speedup 1.0000x reference)
#include <cuda_runtime.h>
#include <cuda_fp16.h>
#include <math.h>
#include <stdint.h>

#define B_ 2
#define N_ 4096
#define C_ 768
#define H_ 12
#define D_ 64
#define M_ (B_*N_)
// 0.125 * log2(e): folded into Q so softmax works in log2 domain
#define QSC_ 0.18033688f
#define ONES2 0x3C003C00u    // half2(1.0, 1.0)

// ---- scratch (allocation-free) ----
__device__ __align__(16) __half g_iq[(size_t)M_*C_], g_ik[(size_t)M_*C_], g_iv[(size_t)M_*C_];
__device__ __align__(16) __half g_wq[(size_t)C_*C_], g_wk[(size_t)C_*C_], g_wv[(size_t)C_*C_];
__device__ __align__(16) __half g_wp[(size_t)C_*C_];
__device__ __align__(16) __half g_q16[(size_t)B_*H_*N_*D_];
__device__ __align__(16) __half g_k16[(size_t)B_*H_*N_*D_];
__device__ __align__(16) __half g_v16[(size_t)B_*H_*N_*D_];
__device__ __align__(16) __half g_x16[(size_t)M_*C_];

__device__ __forceinline__ float gelu_exact(float x) {
    return 0.5f * x * (1.0f + erff(x * 0.70710678118654752f));
}
__device__ __forceinline__ uint32_t smem_u32(const void* p) {
    uint32_t a;
    asm("{ .reg .u64 t; cvta.to.shared.u64 t, %1; cvt.u32.u64 %0, t; }" : "=r"(a) : "l"(p));
    return a;
}
#define CVT_F16X2(res, a, b) \
    asm("cvt.rn.f16x2.f32 %0, %1, %2;" : "=r"(res) : "f"(b), "f"(a))
#define EX2_F16X2(r) \
    asm("ex2.approx.f16x2 %0, %0;" : "+r"(r))

#define LDMATRIX_X4(r0, r1, r2, r3, addr) \
    asm volatile("ldmatrix.sync.aligned.m8n8.x4.shared.b16 {%0,%1,%2,%3}, [%4];" \
        : "=r"(r0), "=r"(r1), "=r"(r2), "=r"(r3) : "r"(addr))
#define LDMATRIX_X4_T(r0, r1, r2, r3, addr) \
    asm volatile("ldmatrix.sync.aligned.m8n8.x4.trans.shared.b16 {%0,%1,%2,%3}, [%4];" \
        : "=r"(r0), "=r"(r1), "=r"(r2), "=r"(r3) : "r"(addr))

__device__ __forceinline__ void mma16816h(float* d, uint32_t a0, uint32_t a1,
                                          uint32_t a2, uint32_t a3,
                                          uint32_t b0, uint32_t b1) {
    asm volatile("mma.sync.aligned.m16n8k16.row.col.f32.f16.f16.f32 "
        "{%0,%1,%2,%3}, {%4,%5,%6,%7}, {%8,%9}, {%0,%1,%2,%3};"
        : "+f"(d[0]), "+f"(d[1]), "+f"(d[2]), "+f"(d[3])
        : "r"(a0), "r"(a1), "r"(a2), "r"(a3), "r"(b0), "r"(b1));
}
#define MMA_F16(d, a, b) \
    asm volatile("mma.sync.aligned.m16n8k16.row.col.f32.f16.f16.f32 " \
        "{%0,%1,%2,%3}, {%4,%5,%6,%7}, {%8,%9}, {%0,%1,%2,%3};" \
        : "+f"((d)[0]), "+f"((d)[1]), "+f"((d)[2]), "+f"((d)[3]) \
        : "r"((a)[0]), "r"((a)[1]), "r"((a)[2]), "r"((a)[3]), "r"((b)[0]), "r"((b)[1]))

__device__ __forceinline__ void cp16(uint32_t saddr, const void* g) {
    asm volatile("cp.async.ca.shared.global [%0], [%1], 16;" :: "r"(saddr), "l"(g));
}
#define CP_COMMIT() asm volatile("cp.async.commit_group;" ::: "memory")
#define CP_WAIT(n)  asm volatile("cp.async.wait_group %0;" :: "n"(n) : "memory")

// ------------------------------------------------ converter (up to 4 tensors)
__global__ void cvtN(const float4* __restrict__ s0, const float4* __restrict__ s1,
                     const float4* __restrict__ s2, const float4* __restrict__ s3,
                     uint2* __restrict__ d0, uint2* __restrict__ d1,
                     uint2* __restrict__ d2, uint2* __restrict__ d3, int n4)
{
    int i = blockIdx.x * blockDim.x + threadIdx.x;
    if (i >= n4) return;
    const float4* in;
    uint2* out;
    switch (blockIdx.y) {
        case 0: in = s0; out = d0; break;
        case 1: in = s1; out = d1; break;
        case 2: in = s2; out = d2; break;
        default: in = s3; out = d3; break;
    }
    float4 v = in[i];
    uint32_t a, b;
    CVT_F16X2(a, v.x, v.y);
    CVT_F16X2(b, v.z, v.w);
    out[i] = make_uint2(a, b);
}

// --------------------------------------- fused 1-pass fp16 QKV projection
// blockIdx.z: 0=Q (*QSC_), 1=K (+bias, gelu), 2=V. BK=64, 2-stage cp.async.
// Epilogue staged through smem -> coalesced STG.128 head-major stores.
#define PROW2 144               // smem row pitch in bytes (64 halves + 8 pad)
#define PTILE2 18432            // 128 * 144
#define ASTAGE2 36864           // X tile + W tile
#define QKV_SMEM 73728          // 2 stages
#define NKC2 (C_/64)            // 12
#define EPIP 136                // epilogue smem pitch in halves (272 B)

__global__ __launch_bounds__(256, 2)
void projQKV(const __half* __restrict__ Xq, const __half* __restrict__ Xk,
             const __half* __restrict__ Xv,
             const __half* __restrict__ Wq, const __half* __restrict__ Wk,
             const __half* __restrict__ Wv,
             const float* __restrict__ bk,
             __half* __restrict__ Oq, __half* __restrict__ Ok, __half* __restrict__ Ov)
{
    extern __shared__ __align__(16) char sm[];
    const uint32_t sb = smem_u32(sm);

    const int z = blockIdx.z;
    const __half* X = (z == 0) ? Xq : (z == 1) ? Xk : Xv;
    const __half* W = (z == 0) ? Wq : (z == 1) ? Wk : Wv;
    __half* outV    = (z == 0) ? Oq : (z == 1) ? Ok : Ov;

    const int m0 = blockIdx.y * 128;
    const int n0 = blockIdx.x * 128;
    const int tid = threadIdx.x;
    const int lane = tid & 31;
    const int warp = tid >> 5;
    const int wm = warp & 1;
    const int wn = warp >> 1;

    const char* src[2] = {
        (const char*)(X + (size_t)m0 * C_), (const char*)(W + (size_t)n0 * C_) };

    float acc[4][4][4];
    #pragma unroll
    for (int i = 0; i < 4; i++)
        #pragma unroll
        for (int j = 0; j < 4; j++)
            #pragma unroll
            for (int e = 0; e < 4; e++) acc[i][j][e] = 0.f;

    #pragma unroll
    for (int u = 0; u < 8; u++) {
        int idx = u * 256 + tid;
        int arr = idx >> 10, rem = idx & 1023;
        int row = rem >> 3, ch = rem & 7;
        cp16(sb + arr * PTILE2 + row * PROW2 + ch * 16,
             src[arr] + (size_t)row * (C_ * 2) + ch * 16);
    }
    CP_COMMIT();

    for (int kc = 0; kc < NKC2; kc++) {
        const int st = kc & 1;
        CP_WAIT(0);
        __syncthreads();
        if (kc + 1 < NKC2) {
            const uint32_t dbase = sb + (st ^ 1) * ASTAGE2;
            const int k0b = (kc + 1) * 128;
            #pragma unroll
            for (int u = 0; u < 8; u++) {
                int idx = u * 256 + tid;
                int arr = idx >> 10, rem = idx & 1023;
                int row = rem >> 3, ch = rem & 7;
                cp16(dbase + arr * PTILE2 + row * PROW2 + ch * 16,
                     src[arr] + (size_t)row * (C_ * 2) + k0b + ch * 16);
            }
            CP_COMMIT();
        }

        const uint32_t abase = sb + st * ASTAGE2;
        const uint32_t aA = abase + (wm * 64 + (lane & 15)) * PROW2 + ((lane >> 4) << 4);
        const uint32_t bA4 = abase + PTILE2
            + (wn * 32 + ((lane >> 4) << 3) + (lane & 7)) * PROW2 + (((lane >> 3) & 1) << 4);

        #pragma unroll
        for (int ks = 0; ks < 4; ks++) {
            const uint32_t koff = ks * 32;
            uint32_t af[4][4], bf[4][2];
            #pragma unroll
            for (int mi = 0; mi < 4; mi++)
                LDMATRIX_X4(af[mi][0], af[mi][1], af[mi][2], af[mi][3],
                            aA + mi * 16 * PROW2 + koff);
            LDMATRIX_X4(bf[0][0], bf[0][1], bf[1][0], bf[1][1], bA4 + koff);
            LDMATRIX_X4(bf[2][0], bf[2][1], bf[3][0], bf[3][1], bA4 + 16 * PROW2 + koff);
            #pragma unroll
            for (int mi = 0; mi < 4; mi++)
                #pragma unroll
                for (int ni = 0; ni < 4; ni++)
                    MMA_F16(acc[mi][ni], af[mi], bf[ni]);
        }
    }

    // ---- epilogue: stage in smem, then coalesced STG.128 head-major stores
    __syncthreads();
    __half* epi = (__half*)sm;
    #pragma unroll
    for (int mi = 0; mi < 4; mi++)
        #pragma unroll
        for (int ni = 0; ni < 4; ni++)
            #pragma unroll
            for (int ep = 0; ep < 2; ep++) {
                int m = wm * 64 + mi * 16 + (lane >> 2) + ep * 8;
                int n = wn * 32 + ni * 8 + (lane & 3) * 2;
                float v0 = acc[mi][ni][ep * 2 + 0];
                float v1 = acc[mi][ni][ep * 2 + 1];
                if (z == 0) { v0 *= QSC_; v1 *= QSC_; }
                else if (z == 1) {
                    v0 = gelu_exact(v0 + bk[n0 + n]);
                    v1 = gelu_exact(v1 + bk[n0 + n + 1]);
                }
                uint32_t vp;
                CVT_F16X2(vp, v0, v1);
                *(uint32_t*)(epi + m * EPIP + n) = vp;
            }
    __syncthreads();

    const int bb = m0 >> 12;
    #pragma unroll
    for (int it = 0; it < 8; it++) {
        int pair = it * 32 + warp * 4 + (lane >> 3);   // 0..255
        int m = pair >> 1;
        int hh = pair & 1;
        uint4 val = *(const uint4*)(epi + m * EPIP + hh * 64 + (lane & 7) * 8);
        int nr = (m0 + m) & (N_ - 1);
        int ng = n0 + hh * 64 + (lane & 7) * 8;
        int h = ng >> 6, d = ng & 63;
        *(uint4*)((char*)outV + ((((size_t)(bb * H_ + h)) * N_ + nr) * D_ + d) * 2) = val;
    }
}

// --------------------------------------- 1-pass final projection (x @ Wp + bp)
#define PROW 80
#define PTILE 10240
#define ASTAGE 20480
#define NKC (C_/32)             // 24

__global__ __launch_bounds__(256, 2)
void projP(const __half* __restrict__ X, const __half* __restrict__ W,
           const float* __restrict__ bias, float* __restrict__ outF)
{
    __shared__ __align__(16) char sm[2 * ASTAGE];
    const uint32_t sb = smem_u32(sm);

    const int m0 = blockIdx.y * 128;
    const int n0 = blockIdx.x * 128;
    const int tid = threadIdx.x;
    const int lane = tid & 31;
    const int warp = tid >> 5;
    const int wm = warp & 1;
    const int wn = warp >> 1;

    const char* src[2] = {
        (const char*)(X + (size_t)m0 * C_), (const char*)(W + (size_t)n0 * C_) };

    float acc[4][4][4];
    #pragma unroll
    for (int i = 0; i < 4; i++)
        #pragma unroll
        for (int j = 0; j < 4; j++)
            #pragma unroll
            for (int e = 0; e < 4; e++) acc[i][j][e] = 0.f;

    #pragma unroll
    for (int u = 0; u < 4; u++) {
        int idx = u * 256 + tid;
        int arr = idx >> 9, rem = idx & 511;
        int row = rem >> 2, ch = rem & 3;
        cp16(sb + arr * PTILE + row * PROW + ch * 16,
             src[arr] + (size_t)row * (C_ * 2) + ch * 16);
    }
    CP_COMMIT();

    for (int kc = 0; kc < NKC; kc++) {
        const int st = kc & 1;
        CP_WAIT(0);
        __syncthreads();
        if (kc + 1 < NKC) {
            const uint32_t dbase = sb + (st ^ 1) * ASTAGE;
            const int k0b = (kc + 1) * 64;
            #pragma unroll
            for (int u = 0; u < 4; u++) {
                int idx = u * 256 + tid;
                int arr = idx >> 9, rem = idx & 511;
                int row = rem >> 2, ch = rem & 3;
                cp16(dbase + arr * PTILE + row * PROW + ch * 16,
                     src[arr] + (size_t)row * (C_ * 2) + k0b + ch * 16);
            }
            CP_COMMIT();
        }

        const uint32_t abase = sb + st * ASTAGE;
        const uint32_t aA = abase + (wm * 64 + (lane & 15)) * PROW + ((lane >> 4) << 4);
        const uint32_t bA4 = abase + PTILE
            + (wn * 32 + ((lane >> 4) << 3) + (lane & 7)) * PROW + (((lane >> 3) & 1) << 4);

        #pragma unroll
        for (int ks = 0; ks < 2; ks++) {
            const uint32_t koff = ks * 32;
            uint32_t af[4][4], bf[4][2];
            #pragma unroll
            for (int mi = 0; mi < 4; mi++)
                LDMATRIX_X4(af[mi][0], af[mi][1], af[mi][2], af[mi][3],
                            aA + mi * 16 * PROW + koff);
            LDMATRIX_X4(bf[0][0], bf[0][1], bf[1][0], bf[1][1], bA4 + koff);
            LDMATRIX_X4(bf[2][0], bf[2][1], bf[3][0], bf[3][1], bA4 + 16 * PROW + koff);
            #pragma unroll
            for (int mi = 0; mi < 4; mi++)
                #pragma unroll
                for (int ni = 0; ni < 4; ni++)
                    MMA_F16(acc[mi][ni], af[mi], bf[ni]);
        }
    }

    #pragma unroll
    for (int mi = 0; mi < 4; mi++)
        #pragma unroll
        for (int ni = 0; ni < 4; ni++)
            #pragma unroll
            for (int ep = 0; ep < 2; ep++) {
                int m = m0 + wm * 64 + mi * 16 + (lane >> 2) + ep * 8;
                int n = n0 + wn * 32 + ni * 8 + (lane & 3) * 2;
                float v0 = acc[mi][ni][ep * 2 + 0] + bias[n];
                float v1 = acc[mi][ni][ep * 2 + 1] + bias[n + 1];
                *(float2*)(outF + (size_t)m * C_ + n) = make_float2(v0, v1);
            }
}

// ------------------------------------------------- HMMA flash attention v4
// q-block 128; 4 warps x 32 q-rows (2 row-groups). 2 CTAs/SM.
// K/V staged in 128-key buffers; two 64-key sub-tiles per barrier.
#define APB 144
#define SQ 0
#define SQSZ (128*APB)                // 18432
#define STILE2A (128*APB)             // 18432 per array (K or V), 128 keys
#define SBUFSZ2 (2*STILE2A)           // 36864 (K128, V128)
#define ATT_SMEM (SQSZ + 2*SBUFSZ2)   // 92160

__global__ __launch_bounds__(128, 2)
void attn_mma(__half* __restrict__ px)
{
    extern __shared__ __align__(16) char sm[];
    const uint32_t sb = smem_u32(sm);

    const int bh = blockIdx.y;
    const int b  = bh / H_, h = bh - b * H_;
    const int q0 = blockIdx.x * 128;
    const int tid = threadIdx.x;
    const int lane = tid & 31;
    const int w = tid >> 5;

    const char* Qg = (const char*)(g_q16 + ((size_t)bh * N_ + q0) * D_);
    const char* src[2] = {
        (const char*)(g_k16 + (size_t)bh * N_ * D_),
        (const char*)(g_v16 + (size_t)bh * N_ * D_) };

    // group Q: 128 rows x 8 chunks = 1024 cp16 / 128 threads
    #pragma unroll
    for (int i = 0; i < 8; i++) {
        int idx = i * 128 + tid;
        int row = idx >> 3, ch = idx & 7;
        cp16(sb + SQ + row * APB + ch * 16, Qg + row * 128 + ch * 16);
    }
    CP_COMMIT();
    // group KV tile 0: 2 arrays x 128 rows x 8 chunks = 2048 cp16
    #pragma unroll
    for (int i = 0; i < 16; i++) {
        int idx = i * 128 + tid;
        int arr = idx >> 10, rem = idx & 1023;
        int row = rem >> 3, ch = rem & 7;
        cp16(sb + SQSZ + arr * STILE2A + row * APB + ch * 16,
             src[arr] + (size_t)row * 128 + ch * 16);
    }
    CP_COMMIT();

    CP_WAIT(1);
    __syncthreads();
    const int wq = w * 32;
    uint32_t qf[2][4][4];
    #pragma unroll
    for (int rg = 0; rg < 2; rg++) {
        const uint32_t aQ = sb + SQ + (wq + rg * 16 + (lane & 15)) * APB + ((lane >> 4) << 4);
        #pragma unroll
        for (int ks = 0; ks < 4; ks++)
            LDMATRIX_X4(qf[rg][ks][0], qf[rg][ks][1], qf[rg][ks][2], qf[rg][ks][3],
                        aQ + ks * 32);
    }

    float o[2][8][4];
    #pragma unroll
    for (int rg = 0; rg < 2; rg++)
        #pragma unroll
        for (int g = 0; g < 8; g++)
            #pragma unroll
            for (int e = 0; e < 4; e++) o[rg][g][e] = 0.f;
    float ol[2][4] = {{0.f,0.f,0.f,0.f},{0.f,0.f,0.f,0.f}};
    float mA[2] = {-1e30f, -1e30f}, mB[2] = {-1e30f, -1e30f};

    const uint32_t rowsel = (lane & 15) * APB + ((lane >> 4) << 4);

    for (int t = 0; t < 32; t++) {
        const int buf = t & 1;
        CP_WAIT(0);
        __syncthreads();
        if (t + 1 < 32) {
            const uint32_t dbase = sb + SQSZ + (1 - buf) * SBUFSZ2;
            const size_t gofs = (size_t)(t + 1) * 128 * 128;
            #pragma unroll
            for (int i = 0; i < 16; i++) {
                int idx = i * 128 + tid;
                int arr = idx >> 10, rem = idx & 1023;
                int row = rem >> 3, ch = rem & 7;
                cp16(dbase + arr * STILE2A + row * APB + ch * 16,
                     src[arr] + gofs + (size_t)row * 128 + ch * 16);
            }
            CP_COMMIT();
        }

        #pragma unroll
        for (int half = 0; half < 2; half++) {
            const uint32_t sK = sb + SQSZ + buf * SBUFSZ2 + half * (64 * APB);
            const uint32_t sV = sb + SQSZ + buf * SBUFSZ2 + STILE2A + half * (64 * APB);

            // ---- S = QK^T (K frags shared across row groups)
            float s[2][8][4];
            #pragma unroll
            for (int rg = 0; rg < 2; rg++)
                #pragma unroll
                for (int f = 0; f < 8; f++)
                    #pragma unroll
                    for (int e = 0; e < 4; e++) s[rg][f][e] = 0.f;

            #pragma unroll
            for (int ks = 0; ks < 4; ks++) {
                #pragma unroll
                for (int p = 0; p < 4; p++) {
                    uint32_t k0, k1, k2, k3;
                    LDMATRIX_X4(k0, k1, k2, k3, sK + (16 * p) * APB + rowsel + ks * 32);
                    mma16816h(s[0][2*p],   qf[0][ks][0], qf[0][ks][1], qf[0][ks][2], qf[0][ks][3], k0, k2);
                    mma16816h(s[0][2*p+1], qf[0][ks][0], qf[0][ks][1], qf[0][ks][2], qf[0][ks][3], k1, k3);
                    mma16816h(s[1][2*p],   qf[1][ks][0], qf[1][ks][1], qf[1][ks][2], qf[1][ks][3], k0, k2);
                    mma16816h(s[1][2*p+1], qf[1][ks][0], qf[1][ks][1], qf[1][ks][2], qf[1][ks][3], k1, k3);
                }
            }

            // ---- online softmax per row group (log2 domain, branchless rescale)
            uint32_t pp[2][8][2];
            #pragma unroll
            for (int rg = 0; rg < 2; rg++) {
                float mxA = -1e30f, mxB = -1e30f;
                #pragma unroll
                for (int f = 0; f < 8; f++) {
                    mxA = fmaxf(mxA, fmaxf(s[rg][f][0], s[rg][f][1]));
                    mxB = fmaxf(mxB, fmaxf(s[rg][f][2], s[rg][f][3]));
                }
                mxA = fmaxf(mxA, __shfl_xor_sync(0xffffffffu, mxA, 1, 4));
                mxA = fmaxf(mxA, __shfl_xor_sync(0xffffffffu, mxA, 2, 4));
                mxB = fmaxf(mxB, __shfl_xor_sync(0xffffffffu, mxB, 1, 4));
                mxB = fmaxf(mxB, __shfl_xor_sync(0xffffffffu, mxB, 2, 4));
                float mnA = fmaxf(mA[rg], mxA), mnB = fmaxf(mB[rg], mxB);
                float alA = exp2f(mA[rg] - mnA), alB = exp2f(mB[rg] - mnB);
                mA[rg] = mnA; mB[rg] = mnB;

                #pragma unroll
                for (int f = 0; f < 8; f++) {
                    CVT_F16X2(pp[rg][f][0], s[rg][f][0] - mnA, s[rg][f][1] - mnA);
                    EX2_F16X2(pp[rg][f][0]);
                    CVT_F16X2(pp[rg][f][1], s[rg][f][2] - mnB, s[rg][f][3] - mnB);
                    EX2_F16X2(pp[rg][f][1]);
                }
                #pragma unroll
                for (int g = 0; g < 8; g++) {
                    o[rg][g][0] *= alA; o[rg][g][1] *= alA;
                    o[rg][g][2] *= alB; o[rg][g][3] *= alB;
                }
                ol[rg][0] *= alA; ol[rg][1] *= alA;
                ol[rg][2] *= alB; ol[rg][3] *= alB;
            }

            // ---- O += P @ V ; l += P @ 1 (V frags shared across row groups)
            #pragma unroll
            for (int kt = 0; kt < 4; kt++) {
                uint32_t a00 = pp[0][2*kt][0], a01 = pp[0][2*kt][1];
                uint32_t a02 = pp[0][2*kt+1][0], a03 = pp[0][2*kt+1][1];
                uint32_t a10 = pp[1][2*kt][0], a11 = pp[1][2*kt][1];
                uint32_t a12 = pp[1][2*kt+1][0], a13 = pp[1][2*kt+1][1];
                #pragma unroll
                for (int g = 0; g < 4; g++) {
                    uint32_t v0, v1, v2, v3;
                    LDMATRIX_X4_T(v0, v1, v2, v3, sV + (16 * kt) * APB + rowsel + g * 32);
                    mma16816h(o[0][2*g],   a00, a01, a02, a03, v0, v1);
                    mma16816h(o[0][2*g+1], a00, a01, a02, a03, v2, v3);
                    mma16816h(o[1][2*g],   a10, a11, a12, a13, v0, v1);
                    mma16816h(o[1][2*g+1], a10, a11, a12, a13, v2, v3);
                }
                mma16816h(ol[0], a00, a01, a02, a03, ONES2, ONES2);
                mma16816h(ol[1], a10, a11, a12, a13, ONES2, ONES2);
            }
        }
    }

    // ---- normalize + write fp16 [B,N,C]
    const int col0 = h * D_ + 2 * (lane & 3);
    #pragma unroll
    for (int rg = 0; rg < 2; rg++) {
        const float ivA = 1.f / ol[rg][0], ivB = 1.f / ol[rg][2];
        const int rowA = q0 + wq + rg * 16 + (lane >> 2);
        #pragma unroll
        for (int g = 0; g < 8; g++) {
            uint32_t vp;
            CVT_F16X2(vp, o[rg][g][0] * ivA, o[rg][g][1] * ivA);
            size_t e = (size_t)(b * N_ + rowA) * C_ + col0 + 8 * g;
            *(uint32_t*)((char*)px + e * 2) = vp;

            CVT_F16X2(vp, o[rg][g][2] * ivB, o[rg][g][3] * ivB);
            e = (size_t)(b * N_ + rowA + 8) * C_ + col0 + 8 * g;
            *(uint32_t*)((char*)px + e * 2) = vp;
        }
    }
}

extern "C" void kernel_launch(void* const* d_in, const int* in_sizes, int n_in,
                              void* d_out, int out_size)
{
    const float* query = (const float*)d_in[0];
    const float* key   = (const float*)d_in[1];
    const float* value = (const float*)d_in[2];
    const float* Wq    = (const float*)d_in[3];
    const float* Wk    = (const float*)d_in[4];
    const float* bk    = (const float*)d_in[5];
    const float* Wv    = (const float*)d_in[6];
    const float* Wp    = (const float*)d_in[7];
    const float* bp    = (const float*)d_in[8];
    float* out = (float*)d_out;

    #define GA(sym) ({ void* _p; cudaGetSymbolAddress(&_p, sym); _p; })
    __half *iq = (__half*)GA(g_iq), *ik = (__half*)GA(g_ik), *iv = (__half*)GA(g_iv);
    __half *wq = (__half*)GA(g_wq), *wk = (__half*)GA(g_wk), *wv = (__half*)GA(g_wv);
    __half *wp = (__half*)GA(g_wp);
    __half *pq = (__half*)GA(g_q16), *pk = (__half*)GA(g_k16), *pv = (__half*)GA(g_v16);
    __half *px = (__half*)GA(g_x16);

    static bool attr_done = false;
    if (!attr_done) {
        cudaFuncSetAttribute(projQKV, cudaFuncAttributeMaxDynamicSharedMemorySize, QKV_SMEM);
        cudaFuncSetAttribute(attn_mma, cudaFuncAttributeMaxDynamicSharedMemorySize, ATT_SMEM);
        attr_done = true;
    }

    const int nx4 = M_ * C_ / 4;
    const int nw4 = C_ * C_ / 4;
    cvtN<<<dim3((nx4 + 255) / 256, 3), 256>>>(
        (const float4*)query, (const float4*)key, (const float4*)value, nullptr,
        (uint2*)iq, (uint2*)ik, (uint2*)iv, nullptr, nx4);
    cvtN<<<dim3((nw4 + 255) / 256, 4), 256>>>(
        (const float4*)Wq, (const float4*)Wk, (const float4*)Wv, (const float4*)Wp,
        (uint2*)wq, (uint2*)wk, (uint2*)wv, (uint2*)wp, nw4);

    projQKV<<<dim3(6, 64, 3), 256, QKV_SMEM>>>(iq, ik, iv, wq, wk, wv, bk, pq, pk, pv);

    attn_mma<<<dim3(32, 24), 128, ATT_SMEM>>>(px);

    projP<<<dim3(6, 64), 256>>>(px, wp, bp, out);
}

// round 17
// speedup vs baseline: 1.0287x; 1.0287x over previous
#include <cuda_runtime.h>
#include <cuda_fp16.h>
#include <math.h>
#include <stdint.h>

#define B_ 2
#define N_ 4096
#define C_ 768
#define H_ 12
#define D_ 64
#define M_ (B_*N_)
// 0.125 * log2(e): folded into Q so softmax works in log2 domain
#define QSC_ 0.18033688f
#define ONES2 0x3C003C00u    // half2(1.0, 1.0)

// ---- scratch (allocation-free) ----
__device__ __align__(16) __half g_iq[(size_t)M_*C_], g_ik[(size_t)M_*C_], g_iv[(size_t)M_*C_];
__device__ __align__(16) __half g_wq[(size_t)C_*C_], g_wk[(size_t)C_*C_], g_wv[(size_t)C_*C_];
__device__ __align__(16) __half g_wp[(size_t)C_*C_];
__device__ __align__(16) __half g_q16[(size_t)B_*H_*N_*D_];
__device__ __align__(16) __half g_k16[(size_t)B_*H_*N_*D_];
__device__ __align__(16) __half g_v16[(size_t)B_*H_*N_*D_];
__device__ __align__(16) __half g_x16[(size_t)M_*C_];

__device__ __forceinline__ float gelu_exact(float x) {
    return 0.5f * x * (1.0f + erff(x * 0.70710678118654752f));
}
__device__ __forceinline__ uint32_t smem_u32(const void* p) {
    uint32_t a;
    asm("{ .reg .u64 t; cvta.to.shared.u64 t, %1; cvt.u32.u64 %0, t; }" : "=r"(a) : "l"(p));
    return a;
}
#define CVT_F16X2(res, a, b) \
    asm("cvt.rn.f16x2.f32 %0, %1, %2;" : "=r"(res) : "f"(b), "f"(a))
#define EX2_F16X2(r) \
    asm("ex2.approx.f16x2 %0, %0;" : "+r"(r))

#define LDMATRIX_X4(r0, r1, r2, r3, addr) \
    asm volatile("ldmatrix.sync.aligned.m8n8.x4.shared.b16 {%0,%1,%2,%3}, [%4];" \
        : "=r"(r0), "=r"(r1), "=r"(r2), "=r"(r3) : "r"(addr))
#define LDMATRIX_X4_T(r0, r1, r2, r3, addr) \
    asm volatile("ldmatrix.sync.aligned.m8n8.x4.trans.shared.b16 {%0,%1,%2,%3}, [%4];" \
        : "=r"(r0), "=r"(r1), "=r"(r2), "=r"(r3) : "r"(addr))

__device__ __forceinline__ void mma16816h(float* d, uint32_t a0, uint32_t a1,
                                          uint32_t a2, uint32_t a3,
                                          uint32_t b0, uint32_t b1) {
    asm volatile("mma.sync.aligned.m16n8k16.row.col.f32.f16.f16.f32 "
        "{%0,%1,%2,%3}, {%4,%5,%6,%7}, {%8,%9}, {%0,%1,%2,%3};"
        : "+f"(d[0]), "+f"(d[1]), "+f"(d[2]), "+f"(d[3])
        : "r"(a0), "r"(a1), "r"(a2), "r"(a3), "r"(b0), "r"(b1));
}
#define MMA_F16(d, a, b) \
    asm volatile("mma.sync.aligned.m16n8k16.row.col.f32.f16.f16.f32 " \
        "{%0,%1,%2,%3}, {%4,%5,%6,%7}, {%8,%9}, {%0,%1,%2,%3};" \
        : "+f"((d)[0]), "+f"((d)[1]), "+f"((d)[2]), "+f"((d)[3]) \
        : "r"((a)[0]), "r"((a)[1]), "r"((a)[2]), "r"((a)[3]), "r"((b)[0]), "r"((b)[1]))

__device__ __forceinline__ void cp16(uint32_t saddr, const void* g) {
    asm volatile("cp.async.ca.shared.global [%0], [%1], 16;" :: "r"(saddr), "l"(g));
}
#define CP_COMMIT() asm volatile("cp.async.commit_group;" ::: "memory")
#define CP_WAIT(n)  asm volatile("cp.async.wait_group %0;" :: "n"(n) : "memory")

// ------------------------------------------------ converter (up to 4 tensors)
__global__ void cvtN(const float4* __restrict__ s0, const float4* __restrict__ s1,
                     const float4* __restrict__ s2, const float4* __restrict__ s3,
                     uint2* __restrict__ d0, uint2* __restrict__ d1,
                     uint2* __restrict__ d2, uint2* __restrict__ d3, int n4)
{
    int i = blockIdx.x * blockDim.x + threadIdx.x;
    if (i >= n4) return;
    const float4* in;
    uint2* out;
    switch (blockIdx.y) {
        case 0: in = s0; out = d0; break;
        case 1: in = s1; out = d1; break;
        case 2: in = s2; out = d2; break;
        default: in = s3; out = d3; break;
    }
    float4 v = in[i];
    uint32_t a, b;
    CVT_F16X2(a, v.x, v.y);
    CVT_F16X2(b, v.z, v.w);
    out[i] = make_uint2(a, b);
}

// --------------------------------------- fused 1-pass fp16 QKV projection
// blockIdx.z: 0=Q (*QSC_), 1=K (+bias, gelu), 2=V. BK=64, 2-stage cp.async.
// Epilogue staged through smem -> coalesced STG.128 head-major stores.
#define PROW2 144               // smem row pitch in bytes (64 halves + 8 pad)
#define PTILE2 18432            // 128 * 144
#define ASTAGE2 36864           // X tile + W tile
#define QKV_SMEM 73728          // 2 stages
#define NKC2 (C_/64)            // 12
#define EPIP 136                // epilogue smem pitch in halves (272 B)

__global__ __launch_bounds__(256, 2)
void projQKV(const __half* __restrict__ Xq, const __half* __restrict__ Xk,
             const __half* __restrict__ Xv,
             const __half* __restrict__ Wq, const __half* __restrict__ Wk,
             const __half* __restrict__ Wv,
             const float* __restrict__ bk,
             __half* __restrict__ Oq, __half* __restrict__ Ok, __half* __restrict__ Ov)
{
    extern __shared__ __align__(16) char sm[];
    const uint32_t sb = smem_u32(sm);

    const int z = blockIdx.z;
    const __half* X = (z == 0) ? Xq : (z == 1) ? Xk : Xv;
    const __half* W = (z == 0) ? Wq : (z == 1) ? Wk : Wv;
    __half* outV    = (z == 0) ? Oq : (z == 1) ? Ok : Ov;

    const int m0 = blockIdx.y * 128;
    const int n0 = blockIdx.x * 128;
    const int tid = threadIdx.x;
    const int lane = tid & 31;
    const int warp = tid >> 5;
    const int wm = warp & 1;
    const int wn = warp >> 1;

    const char* src[2] = {
        (const char*)(X + (size_t)m0 * C_), (const char*)(W + (size_t)n0 * C_) };

    float acc[4][4][4];
    #pragma unroll
    for (int i = 0; i < 4; i++)
        #pragma unroll
        for (int j = 0; j < 4; j++)
            #pragma unroll
            for (int e = 0; e < 4; e++) acc[i][j][e] = 0.f;

    #pragma unroll
    for (int u = 0; u < 8; u++) {
        int idx = u * 256 + tid;
        int arr = idx >> 10, rem = idx & 1023;
        int row = rem >> 3, ch = rem & 7;
        cp16(sb + arr * PTILE2 + row * PROW2 + ch * 16,
             src[arr] + (size_t)row * (C_ * 2) + ch * 16);
    }
    CP_COMMIT();

    for (int kc = 0; kc < NKC2; kc++) {
        const int st = kc & 1;
        CP_WAIT(0);
        __syncthreads();
        if (kc + 1 < NKC2) {
            const uint32_t dbase = sb + (st ^ 1) * ASTAGE2;
            const int k0b = (kc + 1) * 128;
            #pragma unroll
            for (int u = 0; u < 8; u++) {
                int idx = u * 256 + tid;
                int arr = idx >> 10, rem = idx & 1023;
                int row = rem >> 3, ch = rem & 7;
                cp16(dbase + arr * PTILE2 + row * PROW2 + ch * 16,
                     src[arr] + (size_t)row * (C_ * 2) + k0b + ch * 16);
            }
            CP_COMMIT();
        }

        const uint32_t abase = sb + st * ASTAGE2;
        const uint32_t aA = abase + (wm * 64 + (lane & 15)) * PROW2 + ((lane >> 4) << 4);
        const uint32_t bA4 = abase + PTILE2
            + (wn * 32 + ((lane >> 4) << 3) + (lane & 7)) * PROW2 + (((lane >> 3) & 1) << 4);

        #pragma unroll
        for (int ks = 0; ks < 4; ks++) {
            const uint32_t koff = ks * 32;
            uint32_t af[4][4], bf[4][2];
            #pragma unroll
            for (int mi = 0; mi < 4; mi++)
                LDMATRIX_X4(af[mi][0], af[mi][1], af[mi][2], af[mi][3],
                            aA + mi * 16 * PROW2 + koff);
            LDMATRIX_X4(bf[0][0], bf[0][1], bf[1][0], bf[1][1], bA4 + koff);
            LDMATRIX_X4(bf[2][0], bf[2][1], bf[3][0], bf[3][1], bA4 + 16 * PROW2 + koff);
            #pragma unroll
            for (int mi = 0; mi < 4; mi++)
                #pragma unroll
                for (int ni = 0; ni < 4; ni++)
                    MMA_F16(acc[mi][ni], af[mi], bf[ni]);
        }
    }

    // ---- epilogue: stage in smem, then coalesced STG.128 head-major stores
    __syncthreads();
    __half* epi = (__half*)sm;
    #pragma unroll
    for (int mi = 0; mi < 4; mi++)
        #pragma unroll
        for (int ni = 0; ni < 4; ni++)
            #pragma unroll
            for (int ep = 0; ep < 2; ep++) {
                int m = wm * 64 + mi * 16 + (lane >> 2) + ep * 8;
                int n = wn * 32 + ni * 8 + (lane & 3) * 2;
                float v0 = acc[mi][ni][ep * 2 + 0];
                float v1 = acc[mi][ni][ep * 2 + 1];
                if (z == 0) { v0 *= QSC_; v1 *= QSC_; }
                else if (z == 1) {
                    v0 = gelu_exact(v0 + bk[n0 + n]);
                    v1 = gelu_exact(v1 + bk[n0 + n + 1]);
                }
                uint32_t vp;
                CVT_F16X2(vp, v0, v1);
                *(uint32_t*)(epi + m * EPIP + n) = vp;
            }
    __syncthreads();

    const int bb = m0 >> 12;
    #pragma unroll
    for (int it = 0; it < 8; it++) {
        int pair = it * 32 + warp * 4 + (lane >> 3);   // 0..255
        int m = pair >> 1;
        int hh = pair & 1;
        uint4 val = *(const uint4*)(epi + m * EPIP + hh * 64 + (lane & 7) * 8);
        int nr = (m0 + m) & (N_ - 1);
        int ng = n0 + hh * 64 + (lane & 7) * 8;
        int h = ng >> 6, d = ng & 63;
        *(uint4*)((char*)outV + ((((size_t)(bb * H_ + h)) * N_ + nr) * D_ + d) * 2) = val;
    }
}

// --------------------------------------- 1-pass final projection (x @ Wp + bp)
// BK=64, 2-stage cp.async (same config proven on projQKV).
__global__ __launch_bounds__(256, 2)
void projP(const __half* __restrict__ X, const __half* __restrict__ W,
           const float* __restrict__ bias, float* __restrict__ outF)
{
    extern __shared__ __align__(16) char sm[];
    const uint32_t sb = smem_u32(sm);

    const int m0 = blockIdx.y * 128;
    const int n0 = blockIdx.x * 128;
    const int tid = threadIdx.x;
    const int lane = tid & 31;
    const int warp = tid >> 5;
    const int wm = warp & 1;
    const int wn = warp >> 1;

    const char* src[2] = {
        (const char*)(X + (size_t)m0 * C_), (const char*)(W + (size_t)n0 * C_) };

    float acc[4][4][4];
    #pragma unroll
    for (int i = 0; i < 4; i++)
        #pragma unroll
        for (int j = 0; j < 4; j++)
            #pragma unroll
            for (int e = 0; e < 4; e++) acc[i][j][e] = 0.f;

    #pragma unroll
    for (int u = 0; u < 8; u++) {
        int idx = u * 256 + tid;
        int arr = idx >> 10, rem = idx & 1023;
        int row = rem >> 3, ch = rem & 7;
        cp16(sb + arr * PTILE2 + row * PROW2 + ch * 16,
             src[arr] + (size_t)row * (C_ * 2) + ch * 16);
    }
    CP_COMMIT();

    for (int kc = 0; kc < NKC2; kc++) {
        const int st = kc & 1;
        CP_WAIT(0);
        __syncthreads();
        if (kc + 1 < NKC2) {
            const uint32_t dbase = sb + (st ^ 1) * ASTAGE2;
            const int k0b = (kc + 1) * 128;
            #pragma unroll
            for (int u = 0; u < 8; u++) {
                int idx = u * 256 + tid;
                int arr = idx >> 10, rem = idx & 1023;
                int row = rem >> 3, ch = rem & 7;
                cp16(dbase + arr * PTILE2 + row * PROW2 + ch * 16,
                     src[arr] + (size_t)row * (C_ * 2) + k0b + ch * 16);
            }
            CP_COMMIT();
        }

        const uint32_t abase = sb + st * ASTAGE2;
        const uint32_t aA = abase + (wm * 64 + (lane & 15)) * PROW2 + ((lane >> 4) << 4);
        const uint32_t bA4 = abase + PTILE2
            + (wn * 32 + ((lane >> 4) << 3) + (lane & 7)) * PROW2 + (((lane >> 3) & 1) << 4);

        #pragma unroll
        for (int ks = 0; ks < 4; ks++) {
            const uint32_t koff = ks * 32;
            uint32_t af[4][4], bf[4][2];
            #pragma unroll
            for (int mi = 0; mi < 4; mi++)
                LDMATRIX_X4(af[mi][0], af[mi][1], af[mi][2], af[mi][3],
                            aA + mi * 16 * PROW2 + koff);
            LDMATRIX_X4(bf[0][0], bf[0][1], bf[1][0], bf[1][1], bA4 + koff);
            LDMATRIX_X4(bf[2][0], bf[2][1], bf[3][0], bf[3][1], bA4 + 16 * PROW2 + koff);
            #pragma unroll
            for (int mi = 0; mi < 4; mi++)
                #pragma unroll
                for (int ni = 0; ni < 4; ni++)
                    MMA_F16(acc[mi][ni], af[mi], bf[ni]);
        }
    }

    #pragma unroll
    for (int mi = 0; mi < 4; mi++)
        #pragma unroll
        for (int ni = 0; ni < 4; ni++)
            #pragma unroll
            for (int ep = 0; ep < 2; ep++) {
                int m = m0 + wm * 64 + mi * 16 + (lane >> 2) + ep * 8;
                int n = n0 + wn * 32 + ni * 8 + (lane & 3) * 2;
                float v0 = acc[mi][ni][ep * 2 + 0] + bias[n];
                float v1 = acc[mi][ni][ep * 2 + 1] + bias[n + 1];
                *(float2*)(outF + (size_t)m * C_ + n) = make_float2(v0, v1);
            }
}

// ------------------------------------------------- HMMA flash attention v3 (R14)
// q-block 128; 4 warps x 32 q-rows (2 row-groups). 2 CTAs/SM.
// K/V frags shared across row-groups. Branchless rescale.
#define APB 144
#define SQ 0
#define SQSZ (128*APB)                // 18432
#define STILE (64*APB)                // 9216
#define SBUFSZ (2*STILE)              // 18432 (K, V)
#define ATT_SMEM (SQSZ + 2*SBUFSZ)    // 55296

__global__ __launch_bounds__(128, 2)
void attn_mma(__half* __restrict__ px)
{
    extern __shared__ __align__(16) char sm[];
    const uint32_t sb = smem_u32(sm);

    const int bh = blockIdx.y;
    const int b  = bh / H_, h = bh - b * H_;
    const int q0 = blockIdx.x * 128;
    const int tid = threadIdx.x;
    const int lane = tid & 31;
    const int w = tid >> 5;

    const char* Qg = (const char*)(g_q16 + ((size_t)bh * N_ + q0) * D_);
    const char* src[2] = {
        (const char*)(g_k16 + (size_t)bh * N_ * D_),
        (const char*)(g_v16 + (size_t)bh * N_ * D_) };

    #pragma unroll
    for (int i = 0; i < 8; i++) {
        int idx = i * 128 + tid;
        int row = idx >> 3, ch = idx & 7;
        cp16(sb + SQ + row * APB + ch * 16, Qg + row * 128 + ch * 16);
    }
    CP_COMMIT();
    #pragma unroll
    for (int i = 0; i < 8; i++) {
        int idx = i * 128 + tid;
        int arr = idx >> 9, rem = idx & 511;
        int row = rem >> 3, ch = rem & 7;
        cp16(sb + SQSZ + arr * STILE + row * APB + ch * 16,
             src[arr] + (size_t)row * 128 + ch * 16);
    }
    CP_COMMIT();

    CP_WAIT(1);
    __syncthreads();
    const int wq = w * 32;
    uint32_t qf[2][4][4];
    #pragma unroll
    for (int rg = 0; rg < 2; rg++) {
        const uint32_t aQ = sb + SQ + (wq + rg * 16 + (lane & 15)) * APB + ((lane >> 4) << 4);
        #pragma unroll
        for (int ks = 0; ks < 4; ks++)
            LDMATRIX_X4(qf[rg][ks][0], qf[rg][ks][1], qf[rg][ks][2], qf[rg][ks][3],
                        aQ + ks * 32);
    }

    float o[2][8][4];
    #pragma unroll
    for (int rg = 0; rg < 2; rg++)
        #pragma unroll
        for (int g = 0; g < 8; g++)
            #pragma unroll
            for (int e = 0; e < 4; e++) o[rg][g][e] = 0.f;
    float ol[2][4] = {{0.f,0.f,0.f,0.f},{0.f,0.f,0.f,0.f}};
    float mA[2] = {-1e30f, -1e30f}, mB[2] = {-1e30f, -1e30f};

    const uint32_t rowsel = (lane & 15) * APB + ((lane >> 4) << 4);

    for (int t = 0; t < 64; t++) {
        const int buf = t & 1;
        CP_WAIT(0);
        __syncthreads();
        if (t + 1 < 64) {
            const uint32_t dbase = sb + SQSZ + (1 - buf) * SBUFSZ;
            const size_t gofs = (size_t)(t + 1) * 64 * 128;
            #pragma unroll
            for (int i = 0; i < 8; i++) {
                int idx = i * 128 + tid;
                int arr = idx >> 9, rem = idx & 511;
                int row = rem >> 3, ch = rem & 7;
                cp16(dbase + arr * STILE + row * APB + ch * 16,
                     src[arr] + gofs + (size_t)row * 128 + ch * 16);
            }
            CP_COMMIT();
        }

        const uint32_t sK = sb + SQSZ + buf * SBUFSZ;
        const uint32_t sV = sK + STILE;

        // ---- S = QK^T (K frags shared across row groups)
        float s[2][8][4];
        #pragma unroll
        for (int rg = 0; rg < 2; rg++)
            #pragma unroll
            for (int f = 0; f < 8; f++)
                #pragma unroll
                for (int e = 0; e < 4; e++) s[rg][f][e] = 0.f;

        #pragma unroll
        for (int ks = 0; ks < 4; ks++) {
            #pragma unroll
            for (int p = 0; p < 4; p++) {
                uint32_t k0, k1, k2, k3;
                LDMATRIX_X4(k0, k1, k2, k3, sK + (16 * p) * APB + rowsel + ks * 32);
                mma16816h(s[0][2*p],   qf[0][ks][0], qf[0][ks][1], qf[0][ks][2], qf[0][ks][3], k0, k2);
                mma16816h(s[0][2*p+1], qf[0][ks][0], qf[0][ks][1], qf[0][ks][2], qf[0][ks][3], k1, k3);
                mma16816h(s[1][2*p],   qf[1][ks][0], qf[1][ks][1], qf[1][ks][2], qf[1][ks][3], k0, k2);
                mma16816h(s[1][2*p+1], qf[1][ks][0], qf[1][ks][1], qf[1][ks][2], qf[1][ks][3], k1, k3);
            }
        }

        // ---- online softmax per row group (log2 domain, branchless rescale)
        uint32_t pp[2][8][2];
        #pragma unroll
        for (int rg = 0; rg < 2; rg++) {
            float mxA = -1e30f, mxB = -1e30f;
            #pragma unroll
            for (int f = 0; f < 8; f++) {
                mxA = fmaxf(mxA, fmaxf(s[rg][f][0], s[rg][f][1]));
                mxB = fmaxf(mxB, fmaxf(s[rg][f][2], s[rg][f][3]));
            }
            mxA = fmaxf(mxA, __shfl_xor_sync(0xffffffffu, mxA, 1, 4));
            mxA = fmaxf(mxA, __shfl_xor_sync(0xffffffffu, mxA, 2, 4));
            mxB = fmaxf(mxB, __shfl_xor_sync(0xffffffffu, mxB, 1, 4));
            mxB = fmaxf(mxB, __shfl_xor_sync(0xffffffffu, mxB, 2, 4));
            float mnA = fmaxf(mA[rg], mxA), mnB = fmaxf(mB[rg], mxB);
            float alA = exp2f(mA[rg] - mnA), alB = exp2f(mB[rg] - mnB);
            mA[rg] = mnA; mB[rg] = mnB;

            #pragma unroll
            for (int f = 0; f < 8; f++) {
                CVT_F16X2(pp[rg][f][0], s[rg][f][0] - mnA, s[rg][f][1] - mnA);
                EX2_F16X2(pp[rg][f][0]);
                CVT_F16X2(pp[rg][f][1], s[rg][f][2] - mnB, s[rg][f][3] - mnB);
                EX2_F16X2(pp[rg][f][1]);
            }
            #pragma unroll
            for (int g = 0; g < 8; g++) {
                o[rg][g][0] *= alA; o[rg][g][1] *= alA;
                o[rg][g][2] *= alB; o[rg][g][3] *= alB;
            }
            ol[rg][0] *= alA; ol[rg][1] *= alA;
            ol[rg][2] *= alB; ol[rg][3] *= alB;
        }

        // ---- O += P @ V ; l += P @ 1 (V frags shared across row groups)
        #pragma unroll
        for (int kt = 0; kt < 4; kt++) {
            uint32_t a00 = pp[0][2*kt][0], a01 = pp[0][2*kt][1];
            uint32_t a02 = pp[0][2*kt+1][0], a03 = pp[0][2*kt+1][1];
            uint32_t a10 = pp[1][2*kt][0], a11 = pp[1][2*kt][1];
            uint32_t a12 = pp[1][2*kt+1][0], a13 = pp[1][2*kt+1][1];
            #pragma unroll
            for (int g = 0; g < 4; g++) {
                uint32_t v0, v1, v2, v3;
                LDMATRIX_X4_T(v0, v1, v2, v3, sV + (16 * kt) * APB + rowsel + g * 32);
                mma16816h(o[0][2*g],   a00, a01, a02, a03, v0, v1);
                mma16816h(o[0][2*g+1], a00, a01, a02, a03, v2, v3);
                mma16816h(o[1][2*g],   a10, a11, a12, a13, v0, v1);
                mma16816h(o[1][2*g+1], a10, a11, a12, a13, v2, v3);
            }
            mma16816h(ol[0], a00, a01, a02, a03, ONES2, ONES2);
            mma16816h(ol[1], a10, a11, a12, a13, ONES2, ONES2);
        }
    }

    // ---- normalize + write fp16 [B,N,C]
    const int col0 = h * D_ + 2 * (lane & 3);
    #pragma unroll
    for (int rg = 0; rg < 2; rg++) {
        const float ivA = 1.f / ol[rg][0], ivB = 1.f / ol[rg][2];
        const int rowA = q0 + wq + rg * 16 + (lane >> 2);
        #pragma unroll
        for (int g = 0; g < 8; g++) {
            uint32_t vp;
            CVT_F16X2(vp, o[rg][g][0] * ivA, o[rg][g][1] * ivA);
            size_t e = (size_t)(b * N_ + rowA) * C_ + col0 + 8 * g;
            *(uint32_t*)((char*)px + e * 2) = vp;

            CVT_F16X2(vp, o[rg][g][2] * ivB, o[rg][g][3] * ivB);
            e = (size_t)(b * N_ + rowA + 8) * C_ + col0 + 8 * g;
            *(uint32_t*)((char*)px + e * 2) = vp;
        }
    }
}

extern "C" void kernel_launch(void* const* d_in, const int* in_sizes, int n_in,
                              void* d_out, int out_size)
{
    const float* query = (const float*)d_in[0];
    const float* key   = (const float*)d_in[1];
    const float* value = (const float*)d_in[2];
    const float* Wq    = (const float*)d_in[3];
    const float* Wk    = (const float*)d_in[4];
    const float* bk    = (const float*)d_in[5];
    const float* Wv    = (const float*)d_in[6];
    const float* Wp    = (const float*)d_in[7];
    const float* bp    = (const float*)d_in[8];
    float* out = (float*)d_out;

    #define GA(sym) ({ void* _p; cudaGetSymbolAddress(&_p, sym); _p; })
    __half *iq = (__half*)GA(g_iq), *ik = (__half*)GA(g_ik), *iv = (__half*)GA(g_iv);
    __half *wq = (__half*)GA(g_wq), *wk = (__half*)GA(g_wk), *wv = (__half*)GA(g_wv);
    __half *wp = (__half*)GA(g_wp);
    __half *pq = (__half*)GA(g_q16), *pk = (__half*)GA(g_k16), *pv = (__half*)GA(g_v16);
    __half *px = (__half*)GA(g_x16);

    static bool attr_done = false;
    if (!attr_done) {
        cudaFuncSetAttribute(projQKV, cudaFuncAttributeMaxDynamicSharedMemorySize, QKV_SMEM);
        cudaFuncSetAttribute(projP, cudaFuncAttributeMaxDynamicSharedMemorySize, QKV_SMEM);
        cudaFuncSetAttribute(attn_mma, cudaFuncAttributeMaxDynamicSharedMemorySize, ATT_SMEM);
        attr_done = true;
    }

    const int nx4 = M_ * C_ / 4;
    const int nw4 = C_ * C_ / 4;
    cvtN<<<dim3((nx4 + 255) / 256, 3), 256>>>(
        (const float4*)query, (const float4*)key, (const float4*)value, nullptr,
        (uint2*)iq, (uint2*)ik, (uint2*)iv, nullptr, nx4);
    cvtN<<<dim3((nw4 + 255) / 256, 4), 256>>>(
        (const float4*)Wq, (const float4*)Wk, (const float4*)Wv, (const float4*)Wp,
        (uint2*)wq, (uint2*)wk, (uint2*)wv, (uint2*)wp, nw4);

    projQKV<<<dim3(6, 64, 3), 256, QKV_SMEM>>>(iq, ik, iv, wq, wk, wv, bk, pq, pk, pv);

    attn_mma<<<dim3(32, 24), 128, ATT_SMEM>>>(px);

    projP<<<dim3(6, 64), 256, QKV_SMEM>>>(px, wp, bp, out);
}